// round 16
// baseline (speedup 1.0000x reference)
#include <cuda_runtime.h>
#include <cuda_bf16.h>
#include <cstdint>

typedef unsigned long long u64;
typedef unsigned int u32;

// Shapes (fixed): imgs (32,3,512,512) f32; weight (512,16384) f32; bias (512);
// out (32,512) f32.
#define BATCH    32
#define NDIM     512
#define KDIM     16384
#define KSPLIT   32         // GEMM grid.y
#define KCHUNK   512        // k per CTA
#define KSTAGE   64         // k per W pipeline stage
#define NSTAGES  8          // KCHUNK / KSTAGE
#define MTILE    128        // W rows per CTA
#define NWBUF    3          // W pipeline depth (triple buffer)

// GEMM smem strides (bank-conflict-free for the mma fragment access pattern)
#define WSTRIDE  72                     // f32 per W row
#define WSTAGE_F (MTILE * WSTRIDE)      // 9216 f32 = 36864 B per stage
#define BSTRIDE  520                    // bf16 per B row
#define SMEM_W_BYTES (NWBUF * WSTAGE_F * 4)          // 110592
#define SMEM_B_BYTES (BATCH * BSTRIDE * 2)           // 33280 per (hi|lo)
#define SMEM_BYTES (SMEM_W_BYTES + 2 * SMEM_B_BYTES) // 177152

// feats staging: chunk = 16 contiguous image rows = 32 KB, double-buffered
#define FCHUNK_ROWS 16
#define FCHUNK_F    (FCHUNK_ROWS * 512)              // floats per chunk
#define FSMEM_BYTES (2 * FCHUNK_F * 4)               // 65536

// Device scratch (no allocation allowed anywhere)
__device__ __align__(256) __nv_bfloat16 g_fhi[BATCH * KDIM];  // 1 MB feats hi
__device__ __align__(256) __nv_bfloat16 g_flo[BATCH * KDIM];  // 1 MB feats lo
__device__ float g_part[KSPLIT * NDIM * BATCH];               // 2 MB [ks][nout][b]

// ---------------------------------------------------------------------------
// PTX helpers (baseline features only — compute_103 virtual arch, no 'a')
// ---------------------------------------------------------------------------
__device__ __forceinline__ void cp16(void* dst, const void* src) {
    u32 d = (u32)__cvta_generic_to_shared(dst);
    asm volatile("cp.async.ca.shared.global [%0], [%1], 16;\n"
                 :: "r"(d), "l"(src) : "memory");
}
__device__ __forceinline__ void cp_commit() {
    asm volatile("cp.async.commit_group;\n" ::: "memory");
}
template <int N> __device__ __forceinline__ void cp_wait() {
    asm volatile("cp.async.wait_group %0;\n" :: "n"(N) : "memory");
}
// pack two f32 -> bf16x2 reg {lo = v.x, hi = v.y}
__device__ __forceinline__ u32 bf2hi(float2 v) {
    u32 d;
    asm("cvt.rn.bf16x2.f32 %0, %1, %2;" : "=r"(d) : "f"(v.y), "f"(v.x));
    return d;
}
// residual (lo) pair given the hi pair
__device__ __forceinline__ u32 bf2lo(float2 v, u32 h) {
    float h0 = __uint_as_float(h << 16);
    float h1 = __uint_as_float(h & 0xffff0000u);
    float l0 = v.x - h0, l1 = v.y - h1;
    u32 d;
    asm("cvt.rn.bf16x2.f32 %0, %1, %2;" : "=r"(d) : "f"(l1), "f"(l0));
    return d;
}
__device__ __forceinline__ void mma16816(float* c, u32 a0, u32 a1, u32 a2, u32 a3,
                                         u32 b0, u32 b1) {
    asm volatile(
        "mma.sync.aligned.m16n8k16.row.col.f32.bf16.bf16.f32 "
        "{%0,%1,%2,%3}, {%4,%5,%6,%7}, {%8,%9}, {%0,%1,%2,%3};"
        : "+f"(c[0]), "+f"(c[1]), "+f"(c[2]), "+f"(c[3])
        : "r"(a0), "r"(a1), "r"(a2), "r"(a3), "r"(b0), "r"(b1));
}
__device__ __forceinline__ u64 pack4(__nv_bfloat16 a, __nv_bfloat16 b,
                                     __nv_bfloat16 c, __nv_bfloat16 d) {
    return (u64)__bfloat16_as_ushort(a)
         | ((u64)__bfloat16_as_ushort(b) << 16)
         | ((u64)__bfloat16_as_ushort(c) << 32)
         | ((u64)__bfloat16_as_ushort(d) << 48);
}
__device__ __forceinline__ void split1(float f, __nv_bfloat16& h, __nv_bfloat16& l) {
    h = __float2bfloat16(f);
    l = __float2bfloat16(f - __bfloat162float(h));
}

// ---------------------------------------------------------------------------
// Kernel 1 (v3): DCT features via cp.async-staged image chunks.
// Grid 256: CTA = (batch b, slab s of 64 image rows). Loop over 4 chunks of
// 16 contiguous rows (32 KB linear cp.async, double-buffered). Compute from
// smem: 2 threads per 8x8 block (col halves, combined via shfl_xor(1)), then
// bf16 hi/lo 4-packs stored to g_fhi/g_flo [b][k], k = ij*4 + m (u64 stores).
// ---------------------------------------------------------------------------
__global__ __launch_bounds__(256) void feats_kernel(const float* __restrict__ img)
{
    extern __shared__ __align__(16) float fbuf[];   // [2][16][512]

    const int t = threadIdx.x;
    const int b = blockIdx.x >> 3;
    const int s = blockIdx.x & 7;
    const float* ibase = img + (long)b * 786432 + (long)s * 64 * 512;

    // prefetch chunks 0,1
#pragma unroll
    for (int c = 0; c < 2; c++) {
        float* dst = fbuf + c * FCHUNK_F;
        const float* src = ibase + c * FCHUNK_F;
#pragma unroll
        for (int i = 0; i < 8; i++) {
            int idx = (t + i * 256) * 4;            // float offset, 16B units
            cp16(dst + idx, src + idx);
        }
        cp_commit();
    }

    const int half = t & 1;
    const int bl   = t >> 1;        // 0..127: chunk-local block (rb*64 + j)
    const int rb   = bl >> 6;
    const int j    = bl & 63;

    for (int ch = 0; ch < 4; ch++) {
        cp_wait<1>();
        __syncthreads();
        const float* buf = fbuf + (ch & 1) * FCHUNK_F;

        const float* p = buf + (rb * 8) * 512 + j * 8 + half * 4;
        float q0 = 0.f, q1 = 0.f, q2 = 0.f, q3 = 0.f;
#pragma unroll
        for (int r = 0; r < 8; r++) {
            float4 v = *(const float4*)(p + r * 512);
            q0 += v.x; q1 += v.y; q2 += v.z; q3 += v.w;
        }
        float c0 = (q0 + q1) + (q2 + q3);
        float c1 = q0;
        float c2 = q1 - q3;
        float c3 = q0 - q2;

        float o0 = __shfl_xor_sync(0xffffffffu, c0, 1);
        float o1 = __shfl_xor_sync(0xffffffffu, c1, 1);
        float o2 = __shfl_xor_sync(0xffffffffu, c2, 1);
        float o3 = __shfl_xor_sync(0xffffffffu, c3, 1);

        float L0 = half ? o0 : c0, H0 = half ? c0 : o0;
        float L1 = half ? o1 : c1, H1 = half ? c1 : o1;
        float L2 = half ? o2 : c2, H2 = half ? c2 : o2;
        float L3 = half ? o3 : c3, H3 = half ? c3 : o3;

        const float R = 0.70710678118654752f;
        float e = L1 - H1;
        float o = L2 - H2;
        float f0 = 0.125f * (L0 + H0);
        float f1 = 0.125f * (e + R * o);
        float f2 = 0.125f * (L3 + H3);
        float f3 = 0.125f * (e - R * o);

        __nv_bfloat16 h0, l0, h1, l1, h2, l2, h3, l3;
        split1(f0, h0, l0); split1(f1, h1, l1);
        split1(f2, h2, l2); split1(f3, h3, l3);

        int ij = (s * 8 + ch * 2 + rb) * 64 + j;
        long idx = (long)b * KDIM + ij * 4;
        if (half == 0)
            *(u64*)&g_fhi[idx] = pack4(h0, h1, h2, h3);
        else
            *(u64*)&g_flo[idx] = pack4(l0, l1, l2, l3);

        __syncthreads();            // done reading buf before refill
        if (ch + 2 < 4) {
            float* dst = fbuf + (ch & 1) * FCHUNK_F;
            const float* src = ibase + (ch + 2) * FCHUNK_F;
#pragma unroll
            for (int i = 0; i < 8; i++) {
                int idx2 = (t + i * 256) * 4;
                cp16(dst + idx2, src + idx2);
            }
        }
        cp_commit();                // empty groups at tail keep wait<1> aligned
    }
}

// ---------------------------------------------------------------------------
// Kernel 2: split-K GEMM on tensor cores (mma.sync m16n8k16 bf16, HMMA path).
//   D[512 nout, 32 b] = W @ feats^T via 3-term hi/lo split (err ~1e-5).
// grid (4 m-tiles, 32 k-splits), 256 threads. B (feats hi/lo for this k-chunk)
// cp.async'd once; W fp32 TRIPLE-buffered in 64-k stages, converted to bf16
// hi/lo fragments during LDS. Warp w owns m-rows [w*16, w*16+16), all 32 b.
// (Reverted to the proven R14 version.)
// ---------------------------------------------------------------------------
__global__ __launch_bounds__(256, 1) void gemm_kernel(const float* __restrict__ W)
{
    extern __shared__ char sm[];
    float*         sW  = (float*)sm;                                  // [3][128][72]
    __nv_bfloat16* sBh = (__nv_bfloat16*)(sm + SMEM_W_BYTES);         // [32][520]
    __nv_bfloat16* sBl = (__nv_bfloat16*)(sm + SMEM_W_BYTES + SMEM_B_BYTES);

    const int t  = threadIdx.x;
    const int w  = t >> 5, lid = t & 31;
    const int g  = lid >> 2, tg = lid & 3;
    const int mt = blockIdx.x, ks = blockIdx.y;

    const float* Wbase = W + (size_t)(mt * MTILE) * KDIM + ks * KCHUNK;

    // ---- B chunk (hi+lo, 32 x 512 bf16 each) + W stage 0 -> group 0 ----
#pragma unroll
    for (int i = 0; i < 8; i++) {
        int idx = t + i * 256;             // 0..2047 -> 16B chunks
        int br = idx >> 6, c = idx & 63;
        long src = (long)br * KDIM + ks * KCHUNK + c * 8;
        cp16(&sBh[br * BSTRIDE + c * 8], &g_fhi[src]);
        cp16(&sBl[br * BSTRIDE + c * 8], &g_flo[src]);
    }
#pragma unroll
    for (int i = 0; i < 8; i++) {
        int idx = t + i * 256;
        int row = idx >> 4, c4 = idx & 15;
        cp16(&sW[row * WSTRIDE + c4 * 4], Wbase + (size_t)row * KDIM + c4 * 4);
    }
    cp_commit();                           // group 0: B + W0
    // ---- W stages 1,2 -> groups 1,2 ----
#pragma unroll
    for (int s = 1; s < 3; s++) {
#pragma unroll
        for (int i = 0; i < 8; i++) {
            int idx = t + i * 256;
            int row = idx >> 4, c4 = idx & 15;
            cp16(&sW[s * WSTAGE_F + row * WSTRIDE + c4 * 4],
                 Wbase + (size_t)row * KDIM + s * KSTAGE + c4 * 4);
        }
        cp_commit();
    }

    float acc[4][4];
#pragma unroll
    for (int q = 0; q < 4; q++)
#pragma unroll
        for (int r = 0; r < 4; r++) acc[q][r] = 0.f;

    const int wr = w * 16;
    int bufs = 0;   // s % 3

    for (int s = 0; s < NSTAGES; s++) {
        cp_wait<2>();          // oldest pending group (stage s) complete
        __syncthreads();
        const float* sWb = sW + bufs * WSTAGE_F;

#pragma unroll
        for (int k16 = 0; k16 < KSTAGE / 16; k16++) {
            const int k0  = k16 * 16;
            const int kk0 = s * KSTAGE + k0;    // B index within chunk

            // A fragments: fp32 pairs -> bf16 hi/lo
            float2 w00 = *(const float2*)&sWb[(wr + g    ) * WSTRIDE + k0 + tg * 2];
            float2 w01 = *(const float2*)&sWb[(wr + g + 8) * WSTRIDE + k0 + tg * 2];
            float2 w10 = *(const float2*)&sWb[(wr + g    ) * WSTRIDE + k0 + tg * 2 + 8];
            float2 w11 = *(const float2*)&sWb[(wr + g + 8) * WSTRIDE + k0 + tg * 2 + 8];
            u32 ah0 = bf2hi(w00), ah1 = bf2hi(w01), ah2 = bf2hi(w10), ah3 = bf2hi(w11);
            u32 al0 = bf2lo(w00, ah0), al1 = bf2lo(w01, ah1);
            u32 al2 = bf2lo(w10, ah2), al3 = bf2lo(w11, ah3);

#pragma unroll
            for (int q = 0; q < 4; q++) {
                const __nv_bfloat16* bh = &sBh[(q * 8 + g) * BSTRIDE + kk0 + tg * 2];
                const __nv_bfloat16* bl = &sBl[(q * 8 + g) * BSTRIDE + kk0 + tg * 2];
                u32 bh0 = *(const u32*)(bh);
                u32 bh1 = *(const u32*)(bh + 8);
                u32 bl0 = *(const u32*)(bl);
                u32 bl1 = *(const u32*)(bl + 8);

                mma16816(acc[q], ah0, ah1, ah2, ah3, bh0, bh1);  // hi*hi
                mma16816(acc[q], ah0, ah1, ah2, ah3, bl0, bl1);  // hi*lo
                mma16816(acc[q], al0, al1, al2, al3, bh0, bh1);  // lo*hi
            }
        }
        __syncthreads();   // all warps done with buf s before refill

        if (s + 3 < NSTAGES) {   // refill this buffer with stage s+3
            float* dst = sW + bufs * WSTAGE_F;
            const float* src = Wbase + (size_t)(s + 3) * KSTAGE;
#pragma unroll
            for (int i = 0; i < 8; i++) {
                int idx = t + i * 256;
                int row = idx >> 4, c4 = idx & 15;
                cp16(&dst[row * WSTRIDE + c4 * 4],
                     src + (size_t)row * KDIM + c4 * 4);
            }
        }
        cp_commit();       // empty groups at the tail keep wait<2> arithmetic
        bufs = (bufs == 2) ? 0 : bufs + 1;
    }

    // ---- epilogue: g_part[ks][nout][batch]; c0/c1, c2/c3 batch-adjacent ----
    float* op = g_part + (long)ks * (NDIM * BATCH);
    int nout = mt * MTILE + wr + g;
#pragma unroll
    for (int q = 0; q < 4; q++) {
        int bcol = q * 8 + tg * 2;
        *(float2*)&op[(long)nout * BATCH + bcol]       = make_float2(acc[q][0], acc[q][1]);
        *(float2*)&op[(long)(nout + 8) * BATCH + bcol] = make_float2(acc[q][2], acc[q][3]);
    }
}

// ---------------------------------------------------------------------------
// Kernel 3: single-stage split-K reduce (32 -> 1) + bias + transpose.
// ---------------------------------------------------------------------------
__global__ __launch_bounds__(256) void reduce_kernel(const float* __restrict__ bias,
                                                     float* __restrict__ out)
{
    const int i = blockIdx.x * 256 + threadIdx.x;  // 0..16383 = nout*32 + b
    const int nout = i >> 5, b = i & 31;
    const int PL = NDIM * BATCH;

    float a0 = 0.f, a1 = 0.f, a2 = 0.f, a3 = 0.f;
    float a4 = 0.f, a5 = 0.f, a6 = 0.f, a7 = 0.f;
#pragma unroll
    for (int ks = 0; ks < KSPLIT; ks += 8) {
        a0 += g_part[(long)(ks + 0) * PL + i];
        a1 += g_part[(long)(ks + 1) * PL + i];
        a2 += g_part[(long)(ks + 2) * PL + i];
        a3 += g_part[(long)(ks + 3) * PL + i];
        a4 += g_part[(long)(ks + 4) * PL + i];
        a5 += g_part[(long)(ks + 5) * PL + i];
        a6 += g_part[(long)(ks + 6) * PL + i];
        a7 += g_part[(long)(ks + 7) * PL + i];
    }
    float s = (((a0 + a1) + (a2 + a3)) + ((a4 + a5) + (a6 + a7)));
    out[b * NDIM + nout] = s + bias[nout];
}

// ---------------------------------------------------------------------------
extern "C" void kernel_launch(void* const* d_in, const int* in_sizes, int n_in,
                              void* d_out, int out_size)
{
    const float* img    = (const float*)d_in[0];
    const float* weight = (const float*)d_in[1];
    const float* bias   = (const float*)d_in[2];
    float* out = (float*)d_out;

    cudaFuncSetAttribute(feats_kernel,
                         cudaFuncAttributeMaxDynamicSharedMemorySize, FSMEM_BYTES);
    cudaFuncSetAttribute(gemm_kernel,
                         cudaFuncAttributeMaxDynamicSharedMemorySize, SMEM_BYTES);

    feats_kernel<<<256, 256, FSMEM_BYTES>>>(img);
    gemm_kernel<<<dim3(4, KSPLIT), 256, SMEM_BYTES>>>(weight);
    reduce_kernel<<<(NDIM * BATCH) / 256, 256>>>(bias, out);
}

// round 17
// speedup vs baseline: 1.1083x; 1.1083x over previous
#include <cuda_runtime.h>
#include <cuda_bf16.h>
#include <cstdint>

typedef unsigned long long u64;
typedef unsigned int u32;

// Shapes (fixed): imgs (32,3,512,512) f32; weight (512,16384) f32; bias (512);
// out (32,512) f32.
#define BATCH    32
#define NDIM     512
#define KDIM     16384
#define KSPLIT   32         // GEMM grid.y
#define KCHUNK   512        // k per CTA
#define KSTAGE   64         // k per W pipeline stage
#define NSTAGES  8          // KCHUNK / KSTAGE
#define MTILE    128        // W rows per CTA
#define NWBUF    3          // W pipeline depth (triple buffer)

// GEMM smem strides (bank-conflict-free for the mma fragment access pattern)
#define WSTRIDE  72                     // f32 per W row
#define WSTAGE_F (MTILE * WSTRIDE)      // 9216 f32 = 36864 B per stage
#define BSTRIDE  520                    // bf16 per B row
#define SMEM_W_BYTES (NWBUF * WSTAGE_F * 4)          // 110592
#define SMEM_B_BYTES (BATCH * BSTRIDE * 2)           // 33280 per (hi|lo)
#define SMEM_BYTES (SMEM_W_BYTES + 2 * SMEM_B_BYTES) // 177152

// feats staging: chunk = 16 contiguous image rows = 32 KB, double-buffered,
// transferred via cp.async.bulk (UBLKCP) with mbarrier complete_tx.
#define FCHUNK_ROWS 16
#define FCHUNK_F    (FCHUNK_ROWS * 512)              // floats per chunk
#define FCHUNK_B    (FCHUNK_F * 4)                   // 32768 bytes
#define FSMEM_BYTES (2 * FCHUNK_B + 16)              // + 2 mbarriers

// Device scratch (no allocation allowed anywhere)
__device__ __align__(256) __nv_bfloat16 g_fhi[BATCH * KDIM];  // 1 MB feats hi
__device__ __align__(256) __nv_bfloat16 g_flo[BATCH * KDIM];  // 1 MB feats lo
__device__ float g_part[KSPLIT * NDIM * BATCH];               // 2 MB [ks][nout][b]

// ---------------------------------------------------------------------------
// PTX helpers (baseline features only — compute_103 virtual arch, no 'a')
// ---------------------------------------------------------------------------
__device__ __forceinline__ u32 s2u(const void* p) {
    u32 a;
    asm("{ .reg .u64 t; cvta.to.shared.u64 t, %1; cvt.u32.u64 %0, t; }"
        : "=r"(a) : "l"(p));
    return a;
}
__device__ __forceinline__ void cp16(void* dst, const void* src) {
    u32 d = (u32)__cvta_generic_to_shared(dst);
    asm volatile("cp.async.ca.shared.global [%0], [%1], 16;\n"
                 :: "r"(d), "l"(src) : "memory");
}
__device__ __forceinline__ void cp_commit() {
    asm volatile("cp.async.commit_group;\n" ::: "memory");
}
template <int N> __device__ __forceinline__ void cp_wait() {
    asm volatile("cp.async.wait_group %0;\n" :: "n"(N) : "memory");
}
// 1D bulk copy global->shared, completion signaled on mbarrier (UBLKCP path)
__device__ __forceinline__ void bulk_g2s(u32 dst_smem, const void* src,
                                         u32 bytes, u32 mbar) {
    asm volatile(
        "cp.async.bulk.shared::cluster.global.mbarrier::complete_tx::bytes "
        "[%0], [%1], %2, [%3];"
        :: "r"(dst_smem), "l"(src), "r"(bytes), "r"(mbar) : "memory");
}
#define MBAR_INIT(a, c) \
    asm volatile("mbarrier.init.shared.b64 [%0], %1;" :: "r"(a), "r"(c) : "memory")
#define MBAR_EXPECT_TX(a, bytes) \
    asm volatile("mbarrier.arrive.expect_tx.shared.b64 _, [%0], %1;" \
                 :: "r"(a), "r"(bytes) : "memory")
#define MBAR_WAIT(mbar, par) do {                                              \
    u32 _m = (mbar), _p = (par), _d;                                           \
    asm volatile("{\n\t.reg .pred p;\n\t"                                      \
        "mbarrier.try_wait.parity.acquire.cta.shared::cta.b64 p, [%1], %2;\n\t"\
        "selp.b32 %0, 1, 0, p;\n\t}" : "=r"(_d) : "r"(_m), "r"(_p) : "memory");\
    if (!_d) {                                                                 \
        asm volatile("{\n\t.reg .pred P1;\n\tWL%=:\n\t"                        \
            "mbarrier.try_wait.parity.acquire.cta.shared::cta.b64 P1, [%0], %1, 0x989680;\n\t" \
            "@P1 bra.uni WD%=;\n\tbra.uni WL%=;\n\tWD%=:\n\t}"                 \
            :: "r"(_m), "r"(_p) : "memory");                                   \
    }                                                                          \
} while (0)

// pack two f32 -> bf16x2 reg {lo = v.x, hi = v.y}
__device__ __forceinline__ u32 bf2hi(float2 v) {
    u32 d;
    asm("cvt.rn.bf16x2.f32 %0, %1, %2;" : "=r"(d) : "f"(v.y), "f"(v.x));
    return d;
}
// residual (lo) pair given the hi pair
__device__ __forceinline__ u32 bf2lo(float2 v, u32 h) {
    float h0 = __uint_as_float(h << 16);
    float h1 = __uint_as_float(h & 0xffff0000u);
    float l0 = v.x - h0, l1 = v.y - h1;
    u32 d;
    asm("cvt.rn.bf16x2.f32 %0, %1, %2;" : "=r"(d) : "f"(l1), "f"(l0));
    return d;
}
__device__ __forceinline__ void mma16816(float* c, u32 a0, u32 a1, u32 a2, u32 a3,
                                         u32 b0, u32 b1) {
    asm volatile(
        "mma.sync.aligned.m16n8k16.row.col.f32.bf16.bf16.f32 "
        "{%0,%1,%2,%3}, {%4,%5,%6,%7}, {%8,%9}, {%0,%1,%2,%3};"
        : "+f"(c[0]), "+f"(c[1]), "+f"(c[2]), "+f"(c[3])
        : "r"(a0), "r"(a1), "r"(a2), "r"(a3), "r"(b0), "r"(b1));
}
__device__ __forceinline__ u64 pack4(__nv_bfloat16 a, __nv_bfloat16 b,
                                     __nv_bfloat16 c, __nv_bfloat16 d) {
    return (u64)__bfloat16_as_ushort(a)
         | ((u64)__bfloat16_as_ushort(b) << 16)
         | ((u64)__bfloat16_as_ushort(c) << 32)
         | ((u64)__bfloat16_as_ushort(d) << 48);
}
__device__ __forceinline__ void split1(float f, __nv_bfloat16& h, __nv_bfloat16& l) {
    h = __float2bfloat16(f);
    l = __float2bfloat16(f - __bfloat162float(h));
}

// ---------------------------------------------------------------------------
// Kernel 1 (v4): DCT features via cp.async.bulk-staged image chunks.
// Grid 256: CTA = (batch b, slab s of 64 image rows). 4 chunks of 16 rows
// (32 KB), double-buffered; each chunk is ONE cp.async.bulk issued by thread
// 0, completion tracked by a per-buffer mbarrier (expect_tx = 32768).
// Compute from smem: 2 threads per 8x8 block (col halves via shfl_xor(1)),
// bf16 hi/lo 4-packs stored to g_fhi/g_flo [b][k], k = ij*4 + m (u64 stores).
// ---------------------------------------------------------------------------
__global__ __launch_bounds__(256) void feats_kernel(const float* __restrict__ img)
{
    extern __shared__ __align__(16) unsigned char fsm[];
    float* fbuf = (float*)fsm;                       // [2][16][512]
    u64*   mbar = (u64*)(fsm + 2 * FCHUNK_B);        // 2 mbarriers

    const int t = threadIdx.x;
    const int b = blockIdx.x >> 3;
    const int s = blockIdx.x & 7;
    const float* ibase = img + (long)b * 786432 + (long)s * 64 * 512;

    const u32 mb[2] = { s2u(&mbar[0]), s2u(&mbar[1]) };
    const u32 sbuf   = s2u(fbuf);

    if (t == 0) {
        MBAR_INIT(mb[0], 1);
        MBAR_INIT(mb[1], 1);
    }
    __syncthreads();

    if (t == 0) {
#pragma unroll
        for (int c = 0; c < 2; c++) {
            MBAR_EXPECT_TX(mb[c], FCHUNK_B);
            bulk_g2s(sbuf + c * FCHUNK_B, ibase + c * FCHUNK_F, FCHUNK_B, mb[c]);
        }
    }

    const int half = t & 1;
    const int bl   = t >> 1;        // 0..127: chunk-local block (rb*64 + j)
    const int rb   = bl >> 6;
    const int j    = bl & 63;

    for (int ch = 0; ch < 4; ch++) {
        MBAR_WAIT(mb[ch & 1], (ch >> 1) & 1);
        const float* buf = fbuf + (ch & 1) * FCHUNK_F;

        const float* p = buf + (rb * 8) * 512 + j * 8 + half * 4;
        float q0 = 0.f, q1 = 0.f, q2 = 0.f, q3 = 0.f;
#pragma unroll
        for (int r = 0; r < 8; r++) {
            float4 v = *(const float4*)(p + r * 512);
            q0 += v.x; q1 += v.y; q2 += v.z; q3 += v.w;
        }
        float c0 = (q0 + q1) + (q2 + q3);
        float c1 = q0;
        float c2 = q1 - q3;
        float c3 = q0 - q2;

        float o0 = __shfl_xor_sync(0xffffffffu, c0, 1);
        float o1 = __shfl_xor_sync(0xffffffffu, c1, 1);
        float o2 = __shfl_xor_sync(0xffffffffu, c2, 1);
        float o3 = __shfl_xor_sync(0xffffffffu, c3, 1);

        float L0 = half ? o0 : c0, H0 = half ? c0 : o0;
        float L1 = half ? o1 : c1, H1 = half ? c1 : o1;
        float L2 = half ? o2 : c2, H2 = half ? c2 : o2;
        float L3 = half ? o3 : c3, H3 = half ? c3 : o3;

        const float R = 0.70710678118654752f;
        float e = L1 - H1;
        float o = L2 - H2;
        float f0 = 0.125f * (L0 + H0);
        float f1 = 0.125f * (e + R * o);
        float f2 = 0.125f * (L3 + H3);
        float f3 = 0.125f * (e - R * o);

        __nv_bfloat16 h0, l0, h1, l1, h2, l2, h3, l3;
        split1(f0, h0, l0); split1(f1, h1, l1);
        split1(f2, h2, l2); split1(f3, h3, l3);

        int ij = (s * 8 + ch * 2 + rb) * 64 + j;
        long idx = (long)b * KDIM + ij * 4;
        if (half == 0)
            *(u64*)&g_fhi[idx] = pack4(h0, h1, h2, h3);
        else
            *(u64*)&g_flo[idx] = pack4(l0, l1, l2, l3);

        __syncthreads();            // everyone done reading buf before refill
        if (t == 0 && ch + 2 < 4) {
            MBAR_EXPECT_TX(mb[ch & 1], FCHUNK_B);
            bulk_g2s(sbuf + (ch & 1) * FCHUNK_B,
                     ibase + (ch + 2) * FCHUNK_F, FCHUNK_B, mb[ch & 1]);
        }
    }
}

// ---------------------------------------------------------------------------
// Kernel 2: split-K GEMM on tensor cores (mma.sync m16n8k16 bf16, HMMA path).
//   D[512 nout, 32 b] = W @ feats^T via 3-term hi/lo split (err ~1e-5).
// grid (4 m-tiles, 32 k-splits), 256 threads. B (feats hi/lo for this k-chunk)
// cp.async'd once; W fp32 TRIPLE-buffered in 64-k stages, converted to bf16
// hi/lo fragments during LDS. Warp w owns m-rows [w*16, w*16+16), all 32 b.
// (Unchanged — proven R14 version, 19.2 us total.)
// ---------------------------------------------------------------------------
__global__ __launch_bounds__(256, 1) void gemm_kernel(const float* __restrict__ W)
{
    extern __shared__ char sm[];
    float*         sW  = (float*)sm;                                  // [3][128][72]
    __nv_bfloat16* sBh = (__nv_bfloat16*)(sm + SMEM_W_BYTES);         // [32][520]
    __nv_bfloat16* sBl = (__nv_bfloat16*)(sm + SMEM_W_BYTES + SMEM_B_BYTES);

    const int t  = threadIdx.x;
    const int w  = t >> 5, lid = t & 31;
    const int g  = lid >> 2, tg = lid & 3;
    const int mt = blockIdx.x, ks = blockIdx.y;

    const float* Wbase = W + (size_t)(mt * MTILE) * KDIM + ks * KCHUNK;

    // ---- B chunk (hi+lo, 32 x 512 bf16 each) + W stage 0 -> group 0 ----
#pragma unroll
    for (int i = 0; i < 8; i++) {
        int idx = t + i * 256;             // 0..2047 -> 16B chunks
        int br = idx >> 6, c = idx & 63;
        long src = (long)br * KDIM + ks * KCHUNK + c * 8;
        cp16(&sBh[br * BSTRIDE + c * 8], &g_fhi[src]);
        cp16(&sBl[br * BSTRIDE + c * 8], &g_flo[src]);
    }
#pragma unroll
    for (int i = 0; i < 8; i++) {
        int idx = t + i * 256;
        int row = idx >> 4, c4 = idx & 15;
        cp16(&sW[row * WSTRIDE + c4 * 4], Wbase + (size_t)row * KDIM + c4 * 4);
    }
    cp_commit();                           // group 0: B + W0
    // ---- W stages 1,2 -> groups 1,2 ----
#pragma unroll
    for (int s = 1; s < 3; s++) {
#pragma unroll
        for (int i = 0; i < 8; i++) {
            int idx = t + i * 256;
            int row = idx >> 4, c4 = idx & 15;
            cp16(&sW[s * WSTAGE_F + row * WSTRIDE + c4 * 4],
                 Wbase + (size_t)row * KDIM + s * KSTAGE + c4 * 4);
        }
        cp_commit();
    }

    float acc[4][4];
#pragma unroll
    for (int q = 0; q < 4; q++)
#pragma unroll
        for (int r = 0; r < 4; r++) acc[q][r] = 0.f;

    const int wr = w * 16;
    int bufs = 0;   // s % 3

    for (int s = 0; s < NSTAGES; s++) {
        cp_wait<2>();          // oldest pending group (stage s) complete
        __syncthreads();
        const float* sWb = sW + bufs * WSTAGE_F;

#pragma unroll
        for (int k16 = 0; k16 < KSTAGE / 16; k16++) {
            const int k0  = k16 * 16;
            const int kk0 = s * KSTAGE + k0;    // B index within chunk

            // A fragments: fp32 pairs -> bf16 hi/lo
            float2 w00 = *(const float2*)&sWb[(wr + g    ) * WSTRIDE + k0 + tg * 2];
            float2 w01 = *(const float2*)&sWb[(wr + g + 8) * WSTRIDE + k0 + tg * 2];
            float2 w10 = *(const float2*)&sWb[(wr + g    ) * WSTRIDE + k0 + tg * 2 + 8];
            float2 w11 = *(const float2*)&sWb[(wr + g + 8) * WSTRIDE + k0 + tg * 2 + 8];
            u32 ah0 = bf2hi(w00), ah1 = bf2hi(w01), ah2 = bf2hi(w10), ah3 = bf2hi(w11);
            u32 al0 = bf2lo(w00, ah0), al1 = bf2lo(w01, ah1);
            u32 al2 = bf2lo(w10, ah2), al3 = bf2lo(w11, ah3);

#pragma unroll
            for (int q = 0; q < 4; q++) {
                const __nv_bfloat16* bh = &sBh[(q * 8 + g) * BSTRIDE + kk0 + tg * 2];
                const __nv_bfloat16* bl = &sBl[(q * 8 + g) * BSTRIDE + kk0 + tg * 2];
                u32 bh0 = *(const u32*)(bh);
                u32 bh1 = *(const u32*)(bh + 8);
                u32 bl0 = *(const u32*)(bl);
                u32 bl1 = *(const u32*)(bl + 8);

                mma16816(acc[q], ah0, ah1, ah2, ah3, bh0, bh1);  // hi*hi
                mma16816(acc[q], ah0, ah1, ah2, ah3, bl0, bl1);  // hi*lo
                mma16816(acc[q], al0, al1, al2, al3, bh0, bh1);  // lo*hi
            }
        }
        __syncthreads();   // all warps done with buf s before refill

        if (s + 3 < NSTAGES) {   // refill this buffer with stage s+3
            float* dst = sW + bufs * WSTAGE_F;
            const float* src = Wbase + (size_t)(s + 3) * KSTAGE;
#pragma unroll
            for (int i = 0; i < 8; i++) {
                int idx = t + i * 256;
                int row = idx >> 4, c4 = idx & 15;
                cp16(&dst[row * WSTRIDE + c4 * 4],
                     src + (size_t)row * KDIM + c4 * 4);
            }
        }
        cp_commit();       // empty groups at the tail keep wait<2> arithmetic
        bufs = (bufs == 2) ? 0 : bufs + 1;
    }

    // ---- epilogue: g_part[ks][nout][batch]; c0/c1, c2/c3 batch-adjacent ----
    float* op = g_part + (long)ks * (NDIM * BATCH);
    int nout = mt * MTILE + wr + g;
#pragma unroll
    for (int q = 0; q < 4; q++) {
        int bcol = q * 8 + tg * 2;
        *(float2*)&op[(long)nout * BATCH + bcol]       = make_float2(acc[q][0], acc[q][1]);
        *(float2*)&op[(long)(nout + 8) * BATCH + bcol] = make_float2(acc[q][2], acc[q][3]);
    }
}

// ---------------------------------------------------------------------------
// Kernel 3: single-stage split-K reduce (32 -> 1) + bias + transpose.
// ---------------------------------------------------------------------------
__global__ __launch_bounds__(256) void reduce_kernel(const float* __restrict__ bias,
                                                     float* __restrict__ out)
{
    const int i = blockIdx.x * 256 + threadIdx.x;  // 0..16383 = nout*32 + b
    const int nout = i >> 5, b = i & 31;
    const int PL = NDIM * BATCH;

    float a0 = 0.f, a1 = 0.f, a2 = 0.f, a3 = 0.f;
    float a4 = 0.f, a5 = 0.f, a6 = 0.f, a7 = 0.f;
#pragma unroll
    for (int ks = 0; ks < KSPLIT; ks += 8) {
        a0 += g_part[(long)(ks + 0) * PL + i];
        a1 += g_part[(long)(ks + 1) * PL + i];
        a2 += g_part[(long)(ks + 2) * PL + i];
        a3 += g_part[(long)(ks + 3) * PL + i];
        a4 += g_part[(long)(ks + 4) * PL + i];
        a5 += g_part[(long)(ks + 5) * PL + i];
        a6 += g_part[(long)(ks + 6) * PL + i];
        a7 += g_part[(long)(ks + 7) * PL + i];
    }
    float s = (((a0 + a1) + (a2 + a3)) + ((a4 + a5) + (a6 + a7)));
    out[b * NDIM + nout] = s + bias[nout];
}

// ---------------------------------------------------------------------------
extern "C" void kernel_launch(void* const* d_in, const int* in_sizes, int n_in,
                              void* d_out, int out_size)
{
    const float* img    = (const float*)d_in[0];
    const float* weight = (const float*)d_in[1];
    const float* bias   = (const float*)d_in[2];
    float* out = (float*)d_out;

    cudaFuncSetAttribute(feats_kernel,
                         cudaFuncAttributeMaxDynamicSharedMemorySize, FSMEM_BYTES);
    cudaFuncSetAttribute(gemm_kernel,
                         cudaFuncAttributeMaxDynamicSharedMemorySize, SMEM_BYTES);

    feats_kernel<<<256, 256, FSMEM_BYTES>>>(img);
    gemm_kernel<<<dim3(4, KSPLIT), 256, SMEM_BYTES>>>(weight);
    reduce_kernel<<<(NDIM * BATCH) / 256, 256>>>(bias, out);
}